// round 9
// baseline (speedup 1.0000x reference)
#include <cuda_runtime.h>
#include <cuda_bf16.h>

#define B 8
#define C 256
#define HW 2304
#define DK 32
#define C2 512

#define NPREP 8
#define NATTN 576   // 72 tiles x 8 batches

// Scratch (device globals — no allocation allowed; zero-initialized)
__device__ float g_vg[B * C];      // vg = Wv @ GvT
__device__ float g_wqk[B * C];     // wqk = kg @ Wq
__device__ float g_qb[B];          // qb = bq . kg
__device__ float g_lmax, g_lmin;   // reduced once from l
__device__ unsigned int g_flag;    // prep-done counter (reset each launch)
__device__ unsigned int g_done;    // attn-done counter (reset each launch)

__device__ __forceinline__ float ex2f(float x) {
    float y;
    asm("ex2.approx.ftz.f32 %0, %1;" : "=f"(y) : "f"(x));
    return y;
}

__device__ __forceinline__ float warp_sum(float v) {
    #pragma unroll
    for (int o = 16; o; o >>= 1) v += __shfl_xor_sync(0xffffffffu, v, o);
    return v;
}

__device__ __forceinline__ unsigned int ld_acquire_gpu(unsigned int* p) {
    unsigned int v;
    asm volatile("ld.acquire.gpu.u32 %0, [%1];" : "=r"(v) : "l"(p) : "memory");
    return v;
}

// packed f32x2 helpers
__device__ __forceinline__ unsigned long long pack2(float lo, float hi) {
    unsigned long long r;
    asm("mov.b64 %0, {%1, %2};" : "=l"(r) : "f"(lo), "f"(hi));
    return r;
}
__device__ __forceinline__ void unpack2(unsigned long long v, float& lo, float& hi) {
    asm("mov.b64 {%0, %1}, %2;" : "=f"(lo), "=f"(hi) : "l"(v));
}
__device__ __forceinline__ unsigned long long fma2(unsigned long long a,
                                                   unsigned long long b,
                                                   unsigned long long c) {
    unsigned long long d;
    asm("fma.rn.f32x2 %0, %1, %2, %3;" : "=l"(d) : "l"(a), "l"(b), "l"(c));
    return d;
}
__device__ __forceinline__ unsigned long long add2(unsigned long long a,
                                                   unsigned long long b) {
    unsigned long long d;
    asm("add.rn.f32x2 %0, %1, %2;" : "=l"(d) : "l"(a), "l"(b));
    return d;
}

// ---------------------------------------------------------------------------
// Prep path: full text branch for one batch (256 threads).
// ---------------------------------------------------------------------------
__device__ void prep_block(int b, int tid,
                           const float* __restrict__ text,
                           const float* __restrict__ Wg1, const float* __restrict__ bg1,
                           const float* __restrict__ l,
                           const float* __restrict__ ln_g, const float* __restrict__ ln_b,
                           const float* __restrict__ Wg2,  const float* __restrict__ bg2,
                           const float* __restrict__ Wq,   const float* __restrict__ bq,
                           const float* __restrict__ Wk,   const float* __restrict__ Wv)
{
    const int lane = tid & 31, wid = tid >> 5;   // 8 warps

    __shared__ float text_s[C];
    __shared__ float4 part4[2][128];
    __shared__ float t_s[C2];
    __shared__ float gv_s[C];
    __shared__ float part_f[4 * 256];
    __shared__ float kg_s[DK];
    __shared__ float red[8];
    __shared__ float bcast[2];

    // block 0 additionally reduces l min/max (overlaps with text fetch)
    if (b == 0) {
        float mx = -1e30f, mn = 1e30f;
        #pragma unroll
        for (int j = tid; j < HW; j += 256) {
            const float v = l[j];
            mx = fmaxf(mx, v);
            mn = fminf(mn, v);
        }
        #pragma unroll
        for (int o = 16; o; o >>= 1) {
            mx = fmaxf(mx, __shfl_xor_sync(0xffffffffu, mx, o));
            mn = fminf(mn, __shfl_xor_sync(0xffffffffu, mn, o));
        }
        __shared__ float rmx[8], rmn[8];
        if (lane == 0) { rmx[wid] = mx; rmn[wid] = mn; }
        __syncthreads();
        if (tid == 0) {
            float a = rmx[0], b2 = rmn[0];
            #pragma unroll
            for (int k = 1; k < 8; k++) { a = fmaxf(a, rmx[k]); b2 = fminf(b2, rmn[k]); }
            g_lmax = a; g_lmin = b2;
        }
    }

    text_s[tid] = text[b * C + tid];
    __syncthreads();

    // ---- t = text @ Wg1 + bg1 : thread = (cg 0..1, jq 0..127) ----
    {
        const int jq = tid & 127;
        const int cg = tid >> 7;
        const float4* W1 = (const float4*)Wg1;   // [256][128] float4
        float4 acc = make_float4(0.f, 0.f, 0.f, 0.f);
        #pragma unroll 8
        for (int cc = 0; cc < 128; cc++) {
            const int c = cg * 128 + cc;
            const float tk = text_s[c];
            const float4 w = W1[c * 128 + jq];
            acc.x = fmaf(tk, w.x, acc.x);
            acc.y = fmaf(tk, w.y, acc.y);
            acc.z = fmaf(tk, w.z, acc.z);
            acc.w = fmaf(tk, w.w, acc.w);
        }
        part4[cg][jq] = acc;
    }
    __syncthreads();
    if (tid < 128) {
        const float4 p0 = part4[0][tid], p1 = part4[1][tid];
        const float4 bb = ((const float4*)bg1)[tid];
        float4 r;
        r.x = p0.x + p1.x + bb.x;
        r.y = p0.y + p1.y + bb.y;
        r.z = p0.z + p1.z + bb.z;
        r.w = p0.w + p1.w + bb.w;
        ((float4*)t_s)[tid] = r;
    }
    __syncthreads();

    // ---- LayerNorm + exact GELU (each thread owns 2 elements) ----
    const float v0 = t_s[tid], v1 = t_s[tid + 256];
    float s1 = warp_sum(v0 + v1);
    if (lane == 0) red[wid] = s1;
    __syncthreads();
    if (wid == 0) {
        float r = (lane < 8) ? red[lane] : 0.0f;
        r = warp_sum(r);
        if (lane == 0) bcast[0] = r * (1.0f / C2);
    }
    __syncthreads();
    const float mu = bcast[0];
    const float d0 = v0 - mu, d1 = v1 - mu;
    float s2 = warp_sum(d0 * d0 + d1 * d1);
    if (lane == 0) red[wid] = s2;
    __syncthreads();
    if (wid == 0) {
        float r = (lane < 8) ? red[lane] : 0.0f;
        r = warp_sum(r);
        if (lane == 0) bcast[1] = rsqrtf(r * (1.0f / C2) + 1e-5f);
    }
    __syncthreads();
    {
        const float rstd = bcast[1];
        float x0 = d0 * rstd * ln_g[tid] + ln_b[tid];
        float x1 = d1 * rstd * ln_g[tid + 256] + ln_b[tid + 256];
        t_s[tid]       = 0.5f * x0 * (1.0f + erff(x0 * 0.7071067811865476f));
        t_s[tid + 256] = 0.5f * x1 * (1.0f + erff(x1 * 0.7071067811865476f));
    }
    __syncthreads();

    // ---- GvT[c] = sum_k t[k] * Wg2[k*C + c] + bg2[c] ----
    {
        const int q = tid & 63;       // c-quad
        const int h = tid >> 6;       // k-chunk 0..3 (128 k each)
        const float4* W4 = (const float4*)Wg2;   // [512][64] float4
        float4 acc = make_float4(0.f, 0.f, 0.f, 0.f);
        #pragma unroll 8
        for (int kk = 0; kk < 128; kk++) {
            const int k = h * 128 + kk;
            const float tk = t_s[k];
            const float4 w = W4[k * 64 + q];
            acc.x = fmaf(tk, w.x, acc.x);
            acc.y = fmaf(tk, w.y, acc.y);
            acc.z = fmaf(tk, w.z, acc.z);
            acc.w = fmaf(tk, w.w, acc.w);
        }
        part_f[h * 256 + 4 * q + 0] = acc.x;
        part_f[h * 256 + 4 * q + 1] = acc.y;
        part_f[h * 256 + 4 * q + 2] = acc.z;
        part_f[h * 256 + 4 * q + 3] = acc.w;
    }
    __syncthreads();
    {
        float g = bg2[tid];
        #pragma unroll
        for (int h = 0; h < 4; h++) g += part_f[h * 256 + tid];
        gv_s[tid] = g;
    }
    __syncthreads();

    // ---- vg (32 outputs/warp) and kg (4 outputs/warp) ----
    {
        const float4* Wv4 = (const float4*)Wv;        // [256][64] float4
        const float4* gv4 = (const float4*)gv_s;
        const float4 gA = gv4[lane];
        const float4 gB = gv4[32 + lane];
        #pragma unroll 4
        for (int oo = 0; oo < 32; oo++) {
            const int c = wid * 32 + oo;
            const float4 wA = Wv4[c * 64 + lane];
            const float4 wB = Wv4[c * 64 + 32 + lane];
            float p = wA.x * gA.x + wA.y * gA.y + wA.z * gA.z + wA.w * gA.w
                    + wB.x * gB.x + wB.y * gB.y + wB.z * gB.z + wB.w * gB.w;
            p = warp_sum(p);
            if (lane == 0) g_vg[b * C + c] = p;
        }
        const float4* Wk4 = (const float4*)Wk;        // [32][64] float4
        #pragma unroll
        for (int oo = 0; oo < 4; oo++) {
            const int dd = wid * 4 + oo;
            const float4 wA = Wk4[dd * 64 + lane];
            const float4 wB = Wk4[dd * 64 + 32 + lane];
            float p = wA.x * gA.x + wA.y * gA.y + wA.z * gA.z + wA.w * gA.w
                    + wB.x * gB.x + wB.y * gB.y + wB.z * gB.z + wB.w * gB.w;
            p = warp_sum(p);
            if (lane == 0) kg_s[dd] = p;
        }
    }
    __syncthreads();

    // ---- wqk[c] = sum_d kg[d] * Wq[d*C + c];  qb = bq . kg ----
    {
        float acc = 0.0f;
        #pragma unroll
        for (int dd = 0; dd < DK; dd++) acc = fmaf(kg_s[dd], Wq[dd * C + tid], acc);
        g_wqk[b * C + tid] = acc;
    }
    if (wid == 0) {
        float p = bq[lane] * kg_s[lane];
        p = warp_sum(p);
    if (lane == 0) g_qb[b] = p;
    }

    // ---- publish: release ----
    __syncthreads();
    if (tid == 0) {
        __threadfence();
        atomicAdd(&g_flag, 1u);
    }
}

// ---------------------------------------------------------------------------
// Fused kernel. Blocks 0..7: prep (batch = blockIdx.x). Blocks 8..583: attn.
// Prep blocks have the lowest indices -> wave-1 residency -> no deadlock.
// ---------------------------------------------------------------------------
__global__ __launch_bounds__(256, 4)
void fused_kernel(const float* __restrict__ img,
                  const float* __restrict__ text,
                  const float* __restrict__ l,
                  const float* __restrict__ Wg1, const float* __restrict__ bg1,
                  const float* __restrict__ ln_g, const float* __restrict__ ln_b,
                  const float* __restrict__ Wg2, const float* __restrict__ bg2,
                  const float* __restrict__ Wq,  const float* __restrict__ bq,
                  const float* __restrict__ Wk,  const float* __restrict__ Wv,
                  const float* __restrict__ bv,
                  const float* __restrict__ gamma_p,
                  float* __restrict__ out)
{
    const int tid = threadIdx.x;

    if (blockIdx.x < NPREP) {
        prep_block(blockIdx.x, tid, text, Wg1, bg1, l, ln_g, ln_b,
                   Wg2, bg2, Wq, bq, Wk, Wv);
        return;
    }

    // ---------------- attn block ----------------
    const int idx = blockIdx.x - NPREP;     // 0..575
    const int bx = idx % 72;
    const int b  = idx / 72;
    const int p = tid & 31;      // pixel within block (lane)
    const int s = tid >> 5;      // split 0..7 (warp)
    const int i = bx * 32 + p;
    const int c0 = s * 32;

    __shared__ float2 ls2[HW / 2];
    __shared__ float wq[C];
    __shared__ float vgs[C];
    __shared__ float bvs[C];
    __shared__ float partA[256];
    __shared__ float partS[256];
    __shared__ float partT[256];

    // ---- pre-wait phase: independent of prep ----
    float im[32];
    const float* xb = img + (size_t)b * C * HW + (size_t)c0 * HW + i;
    #pragma unroll
    for (int cc = 0; cc < 32; cc++) im[cc] = xb[(size_t)cc * HW];

    {
        float* lsf = (float*)ls2;
        #pragma unroll
        for (int j = tid; j < HW; j += 256) lsf[j] = l[j];
    }
    bvs[tid] = bv[tid];
    const float gm = *gamma_p;

    // ---- wait for all prep blocks ----
    if (tid == 0) {
        while (ld_acquire_gpu(&g_flag) < NPREP) __nanosleep(64);
    }
    __syncthreads();
    __threadfence();   // order: flag observation -> subsequent global reads

    const float qb   = g_qb[b];
    const float lmax = g_lmax;
    const float lmin = g_lmin;
    wq[tid]  = g_wqk[b * C + tid];
    vgs[tid] = g_vg[b * C + tid];
    __syncthreads();

    // partial dot over this thread's 32 channels
    float a = 0.0f;
    #pragma unroll
    for (int cc = 0; cc < 32; cc++) a = fmaf(wq[c0 + cc], im[cc], a);
    partA[tid] = a;
    __syncthreads();
    float af = qb;
    #pragma unroll
    for (int k = 0; k < 8; k++) af += partA[k * 32 + p];

    // softmax-weighted sum of l (rank-1 logits), exp2 domain, f32x2-packed
    const float al = af * 1.4426950408889634f;
    const float m2 = (al > 0.0f) ? al * lmax : al * lmin;
    const unsigned long long al2  = pack2(al, al);
    const unsigned long long m2n2 = pack2(-m2, -m2);
    unsigned long long S2 = pack2(0.0f, 0.0f);
    unsigned long long T2 = S2;
    const int base2 = s * (HW / 16);
    #pragma unroll 8
    for (int jj = 0; jj < HW / 16; jj++) {
        const float2 lj2f = ls2[base2 + jj];
        const unsigned long long lj2 = pack2(lj2f.x, lj2f.y);
        const unsigned long long u2 = fma2(al2, lj2, m2n2);
        float u0, u1;
        unpack2(u2, u0, u1);
        const unsigned long long e2 = pack2(ex2f(u0), ex2f(u1));
        S2 = add2(S2, e2);
        T2 = fma2(lj2, e2, T2);
    }
    float S0, S1, T0, T1;
    unpack2(S2, S0, S1);
    unpack2(T2, T0, T1);
    partS[tid] = S0 + S1;
    partT[tid] = T0 + T1;
    __syncthreads();
    float Ss = 0.0f, Ts = 0.0f;
    #pragma unroll
    for (int k = 0; k < 8; k++) {
        Ss += partS[k * 32 + p];
        Ts += partT[k * 32 + p];
    }
    const float sv = Ts / Ss;

    // out = img + gamma * (vg*sv + bv), register-cached img
    float* ob = out + (size_t)b * C * HW + (size_t)c0 * HW + i;
    #pragma unroll
    for (int cc = 0; cc < 32; cc++) {
        ob[(size_t)cc * HW] = fmaf(gm, fmaf(vgs[c0 + cc], sv, bvs[c0 + cc]), im[cc]);
    }

    // ---- reset flags for next launch: last attn block to finish does it ----
    if (tid == 0) {
        const unsigned int old = atomicAdd(&g_done, 1u);
        if (old == NATTN - 1) {
            g_flag = 0;
            g_done = 0;
        }
    }
}

extern "C" void kernel_launch(void* const* d_in, const int* in_sizes, int n_in,
                              void* d_out, int out_size)
{
    const float* img   = (const float*)d_in[0];
    const float* text  = (const float*)d_in[1];
    const float* l     = (const float*)d_in[2];
    const float* Wg1   = (const float*)d_in[3];
    const float* bg1   = (const float*)d_in[4];
    const float* ln_g  = (const float*)d_in[5];
    const float* ln_b  = (const float*)d_in[6];
    const float* Wg2   = (const float*)d_in[7];
    const float* bg2   = (const float*)d_in[8];
    const float* Wq    = (const float*)d_in[9];
    const float* bq    = (const float*)d_in[10];
    const float* Wk    = (const float*)d_in[11];
    // d_in[12] = bk : cancels in softmax, unused
    const float* Wv    = (const float*)d_in[13];
    const float* bv    = (const float*)d_in[14];
    const float* gamma = (const float*)d_in[15];
    float* out = (float*)d_out;

    fused_kernel<<<NPREP + NATTN, 256>>>(img, text, l, Wg1, bg1, ln_g, ln_b,
                                         Wg2, bg2, Wq, bq, Wk, Wv, bv, gamma, out);
}

// round 10
// speedup vs baseline: 1.0935x; 1.0935x over previous
#include <cuda_runtime.h>
#include <cuda_bf16.h>

#define B 8
#define C 256
#define HW 2304
#define DK 32
#define C2 512

#define NP1   128                    // wide t-partial blocks (16 per batch)
#define NP2   8                      // per-batch combine blocks
#define NATTN 576                    // 72 tiles x 8 batches
#define NBLK  (NP1 + NP2 + NATTN)    // 712

// Scratch (device globals — zero-initialized; counters reset each launch)
__device__ float g_tp[8 * B * C2];   // p1 partials: [ct][b][j]
__device__ float g_vg[B * C];
__device__ float g_wqk[B * C];
__device__ float g_qb[B];
__device__ float g_lmax, g_lmin;
__device__ unsigned int g_cnt1[B];   // per-batch p1-done counters
__device__ unsigned int g_flag2;     // combine-done counter
__device__ unsigned int g_done;      // attn-done counter

__device__ __forceinline__ float ex2f(float x) {
    float y;
    asm("ex2.approx.ftz.f32 %0, %1;" : "=f"(y) : "f"(x));
    return y;
}

__device__ __forceinline__ float warp_sum(float v) {
    #pragma unroll
    for (int o = 16; o; o >>= 1) v += __shfl_xor_sync(0xffffffffu, v, o);
    return v;
}

__device__ __forceinline__ unsigned int ld_acquire_gpu(unsigned int* p) {
    unsigned int v;
    asm volatile("ld.acquire.gpu.u32 %0, [%1];" : "=r"(v) : "l"(p) : "memory");
    return v;
}

// packed f32x2 helpers
__device__ __forceinline__ unsigned long long pack2(float lo, float hi) {
    unsigned long long r;
    asm("mov.b64 %0, {%1, %2};" : "=l"(r) : "f"(lo), "f"(hi));
    return r;
}
__device__ __forceinline__ void unpack2(unsigned long long v, float& lo, float& hi) {
    asm("mov.b64 {%0, %1}, %2;" : "=f"(lo), "=f"(hi) : "l"(v));
}
__device__ __forceinline__ unsigned long long fma2(unsigned long long a,
                                                   unsigned long long b,
                                                   unsigned long long c) {
    unsigned long long d;
    asm("fma.rn.f32x2 %0, %1, %2, %3;" : "=l"(d) : "l"(a), "l"(b), "l"(c));
    return d;
}
__device__ __forceinline__ unsigned long long add2(unsigned long long a,
                                                   unsigned long long b) {
    unsigned long long d;
    asm("add.rn.f32x2 %0, %1, %2;" : "=l"(d) : "l"(a), "l"(b));
    return d;
}

// ---------------------------------------------------------------------------
// Stage 1: wide t-partials (identical shape to R8 p1). blk = 0..127.
// ---------------------------------------------------------------------------
__device__ void p1_block(int blk, int tid,
                         const float* __restrict__ text,
                         const float* __restrict__ Wg1)
{
    const int b  = blk >> 4;
    const int jh = (blk >> 3) & 1;
    const int ct = blk & 7;
    const int j  = jh * 256 + tid;

    __shared__ float text_s[32];
    if (tid < 32) text_s[tid] = text[b * C + ct * 32 + tid];
    __syncthreads();

    float acc = 0.0f;
    #pragma unroll
    for (int cc = 0; cc < 32; cc++) {
        acc = fmaf(text_s[cc], Wg1[(ct * 32 + cc) * C2 + j], acc);
    }
    g_tp[ct * (B * C2) + b * C2 + j] = acc;

    __syncthreads();
    if (tid == 0) {
        __threadfence();
        atomicAdd(&g_cnt1[b], 1u);
    }
}

// ---------------------------------------------------------------------------
// Stage 2: per-batch combine (256 threads). blk-NP1 = batch.
// ---------------------------------------------------------------------------
__device__ void p2_block(int b, int tid,
                         const float* __restrict__ l,
                         const float* __restrict__ bg1,
                         const float* __restrict__ ln_g, const float* __restrict__ ln_b,
                         const float* __restrict__ Wg2,  const float* __restrict__ bg2,
                         const float* __restrict__ Wq,   const float* __restrict__ bq,
                         const float* __restrict__ Wk,   const float* __restrict__ Wv)
{
    const int lane = tid & 31, wid = tid >> 5;   // 8 warps

    __shared__ float t_s[C2];
    __shared__ float gv_s[C];
    __shared__ float part_f[4 * 256];
    __shared__ float kg_s[DK];
    __shared__ float red[8];
    __shared__ float bcast[2];

    // batch-0 combine block also reduces l min/max (before its spin)
    if (b == 0) {
        __shared__ float rmx[8], rmn[8];
        float mx = -1e30f, mn = 1e30f;
        #pragma unroll
        for (int j = tid; j < HW; j += 256) {
            const float v = l[j];
            mx = fmaxf(mx, v);
            mn = fminf(mn, v);
        }
        #pragma unroll
        for (int o = 16; o; o >>= 1) {
            mx = fmaxf(mx, __shfl_xor_sync(0xffffffffu, mx, o));
            mn = fminf(mn, __shfl_xor_sync(0xffffffffu, mn, o));
        }
        if (lane == 0) { rmx[wid] = mx; rmn[wid] = mn; }
        __syncthreads();
        if (tid == 0) {
            float a = rmx[0], b2 = rmn[0];
            #pragma unroll
            for (int k = 1; k < 8; k++) { a = fmaxf(a, rmx[k]); b2 = fminf(b2, rmn[k]); }
            g_lmax = a; g_lmin = b2;
        }
    }

    // wait for this batch's 16 p1 blocks
    if (tid == 0) {
        while (ld_acquire_gpu(&g_cnt1[b]) < 16u) __nanosleep(32);
    }
    __syncthreads();
    __threadfence();

    // ---- combine partials + bias (each thread: 2 j's) ----
    {
        float v0 = bg1[tid], v1 = bg1[tid + 256];
        #pragma unroll
        for (int ct = 0; ct < 8; ct++) {
            v0 += g_tp[ct * (B * C2) + b * C2 + tid];
            v1 += g_tp[ct * (B * C2) + b * C2 + tid + 256];
        }
        t_s[tid] = v0;
        t_s[tid + 256] = v1;
    }
    __syncthreads();

    // ---- LayerNorm + exact GELU ----
    const float v0 = t_s[tid], v1 = t_s[tid + 256];
    float s1 = warp_sum(v0 + v1);
    if (lane == 0) red[wid] = s1;
    __syncthreads();
    if (wid == 0) {
        float r = (lane < 8) ? red[lane] : 0.0f;
        r = warp_sum(r);
        if (lane == 0) bcast[0] = r * (1.0f / C2);
    }
    __syncthreads();
    const float mu = bcast[0];
    const float d0 = v0 - mu, d1 = v1 - mu;
    float s2 = warp_sum(d0 * d0 + d1 * d1);
    if (lane == 0) red[wid] = s2;
    __syncthreads();
    if (wid == 0) {
        float r = (lane < 8) ? red[lane] : 0.0f;
        r = warp_sum(r);
        if (lane == 0) bcast[1] = rsqrtf(r * (1.0f / C2) + 1e-5f);
    }
    __syncthreads();
    {
        const float rstd = bcast[1];
        float x0 = d0 * rstd * ln_g[tid] + ln_b[tid];
        float x1 = d1 * rstd * ln_g[tid + 256] + ln_b[tid + 256];
        t_s[tid]       = 0.5f * x0 * (1.0f + erff(x0 * 0.7071067811865476f));
        t_s[tid + 256] = 0.5f * x1 * (1.0f + erff(x1 * 0.7071067811865476f));
    }
    __syncthreads();

    // ---- GvT[c] = sum_k t[k] * Wg2[k*C+c] + bg2[c] ----
    // thread = (k-chunk h of 128, c-quad q); 4 independent accumulators (ILP)
    {
        const int q = tid & 63;
        const int h = tid >> 6;
        const float4* W4 = (const float4*)Wg2;   // [512][64] float4
        float4 a0 = make_float4(0,0,0,0), a1 = a0, a2 = a0, a3 = a0;
        const int k0 = h * 128;
        #pragma unroll 32
        for (int kk = 0; kk < 32; kk++) {
            const float t0 = t_s[k0 + kk];
            const float t1 = t_s[k0 + 32 + kk];
            const float t2 = t_s[k0 + 64 + kk];
            const float t3 = t_s[k0 + 96 + kk];
            const float4 w0 = W4[(k0 + kk) * 64 + q];
            const float4 w1 = W4[(k0 + 32 + kk) * 64 + q];
            const float4 w2 = W4[(k0 + 64 + kk) * 64 + q];
            const float4 w3 = W4[(k0 + 96 + kk) * 64 + q];
            a0.x = fmaf(t0, w0.x, a0.x); a0.y = fmaf(t0, w0.y, a0.y);
            a0.z = fmaf(t0, w0.z, a0.z); a0.w = fmaf(t0, w0.w, a0.w);
            a1.x = fmaf(t1, w1.x, a1.x); a1.y = fmaf(t1, w1.y, a1.y);
            a1.z = fmaf(t1, w1.z, a1.z); a1.w = fmaf(t1, w1.w, a1.w);
            a2.x = fmaf(t2, w2.x, a2.x); a2.y = fmaf(t2, w2.y, a2.y);
            a2.z = fmaf(t2, w2.z, a2.z); a2.w = fmaf(t2, w2.w, a2.w);
            a3.x = fmaf(t3, w3.x, a3.x); a3.y = fmaf(t3, w3.y, a3.y);
            a3.z = fmaf(t3, w3.z, a3.z); a3.w = fmaf(t3, w3.w, a3.w);
        }
        part_f[h * 256 + 4 * q + 0] = a0.x + a1.x + a2.x + a3.x;
        part_f[h * 256 + 4 * q + 1] = a0.y + a1.y + a2.y + a3.y;
        part_f[h * 256 + 4 * q + 2] = a0.z + a1.z + a2.z + a3.z;
        part_f[h * 256 + 4 * q + 3] = a0.w + a1.w + a2.w + a3.w;
    }
    __syncthreads();
    {
        float g = bg2[tid];
        #pragma unroll
        for (int h = 0; h < 4; h++) g += part_f[h * 256 + tid];
        gv_s[tid] = g;
    }
    __syncthreads();

    // ---- vg (32 outputs/warp) and kg (4 outputs/warp) ----
    {
        const float4* Wv4 = (const float4*)Wv;        // [256][64] float4
        const float4* gv4 = (const float4*)gv_s;
        const float4 gA = gv4[lane];
        const float4 gB = gv4[32 + lane];
        #pragma unroll 8
        for (int oo = 0; oo < 32; oo++) {
            const int c = wid * 32 + oo;
            const float4 wA = Wv4[c * 64 + lane];
            const float4 wB = Wv4[c * 64 + 32 + lane];
            float p = wA.x * gA.x + wA.y * gA.y + wA.z * gA.z + wA.w * gA.w
                    + wB.x * gB.x + wB.y * gB.y + wB.z * gB.z + wB.w * gB.w;
            p = warp_sum(p);
            if (lane == 0) g_vg[b * C + c] = p;
        }
        const float4* Wk4 = (const float4*)Wk;        // [32][64] float4
        #pragma unroll
        for (int oo = 0; oo < 4; oo++) {
            const int dd = wid * 4 + oo;
            const float4 wA = Wk4[dd * 64 + lane];
            const float4 wB = Wk4[dd * 64 + 32 + lane];
            float p = wA.x * gA.x + wA.y * gA.y + wA.z * gA.z + wA.w * gA.w
                    + wB.x * gB.x + wB.y * gB.y + wB.z * gB.z + wB.w * gB.w;
            p = warp_sum(p);
            if (lane == 0) kg_s[dd] = p;
        }
    }
    __syncthreads();

    // ---- wqk[c] = sum_d kg[d] * Wq[d*C+c]; qb = bq . kg ----
    {
        float acc = 0.0f;
        #pragma unroll
        for (int dd = 0; dd < DK; dd++) acc = fmaf(kg_s[dd], Wq[dd * C + tid], acc);
        g_wqk[b * C + tid] = acc;
    }
    if (wid == 0) {
        float p = bq[lane] * kg_s[lane];
        p = warp_sum(p);
        if (lane == 0) g_qb[b] = p;
    }

    __syncthreads();
    if (tid == 0) {
        __threadfence();
        atomicAdd(&g_flag2, 1u);
    }
}

// ---------------------------------------------------------------------------
// Fused kernel: 712 blocks x 256 threads.
// 0..127 p1 | 128..135 combine | 136..711 attn.
// ---------------------------------------------------------------------------
__global__ __launch_bounds__(256, 4)
void fused_kernel(const float* __restrict__ img,
                  const float* __restrict__ text,
                  const float* __restrict__ l,
                  const float* __restrict__ Wg1, const float* __restrict__ bg1,
                  const float* __restrict__ ln_g, const float* __restrict__ ln_b,
                  const float* __restrict__ Wg2, const float* __restrict__ bg2,
                  const float* __restrict__ Wq,  const float* __restrict__ bq,
                  const float* __restrict__ Wk,  const float* __restrict__ Wv,
                  const float* __restrict__ bv,
                  const float* __restrict__ gamma_p,
                  float* __restrict__ out)
{
    const int tid = threadIdx.x;

    if (blockIdx.x < NP1) {
        p1_block(blockIdx.x, tid, text, Wg1);
        return;
    }
    if (blockIdx.x < NP1 + NP2) {
        p2_block(blockIdx.x - NP1, tid, l, bg1, ln_g, ln_b,
                 Wg2, bg2, Wq, bq, Wk, Wv);
        return;
    }

    // ---------------- attn block ----------------
    const int idx = blockIdx.x - (NP1 + NP2);   // 0..575
    const int bx = idx % 72;
    const int b  = idx / 72;
    const int p = tid & 31;      // pixel within block (lane)
    const int s = tid >> 5;      // split 0..7 (warp)
    const int i = bx * 32 + p;
    const int c0 = s * 32;

    __shared__ float2 ls2[HW / 2];
    __shared__ float wq[C];
    __shared__ float vgs[C];
    __shared__ float bvs[C];
    __shared__ float partA[256];
    __shared__ float partS[256];
    __shared__ float partT[256];

    // ---- pre-wait phase: independent of prep ----
    float im[32];
    const float* xb = img + (size_t)b * C * HW + (size_t)c0 * HW + i;
    #pragma unroll
    for (int cc = 0; cc < 32; cc++) im[cc] = xb[(size_t)cc * HW];

    {
        float* lsf = (float*)ls2;
        #pragma unroll
        for (int j = tid; j < HW; j += 256) lsf[j] = l[j];
    }
    bvs[tid] = bv[tid];
    const float gm = *gamma_p;

    // ---- wait for all combine blocks ----
    if (tid == 0) {
        while (ld_acquire_gpu(&g_flag2) < NP2) __nanosleep(64);
    }
    __syncthreads();
    __threadfence();

    const float qb   = g_qb[b];
    const float lmax = g_lmax;
    const float lmin = g_lmin;
    wq[tid]  = g_wqk[b * C + tid];
    vgs[tid] = g_vg[b * C + tid];
    __syncthreads();

    // partial dot over this thread's 32 channels
    float a = 0.0f;
    #pragma unroll
    for (int cc = 0; cc < 32; cc++) a = fmaf(wq[c0 + cc], im[cc], a);
    partA[tid] = a;
    __syncthreads();
    float af = qb;
    #pragma unroll
    for (int k = 0; k < 8; k++) af += partA[k * 32 + p];

    // softmax-weighted sum of l (rank-1 logits), exp2 domain, f32x2-packed
    const float al = af * 1.4426950408889634f;
    const float m2 = (al > 0.0f) ? al * lmax : al * lmin;
    const unsigned long long al2  = pack2(al, al);
    const unsigned long long m2n2 = pack2(-m2, -m2);
    unsigned long long S2 = pack2(0.0f, 0.0f);
    unsigned long long T2 = S2;
    const int base2 = s * (HW / 16);
    #pragma unroll 8
    for (int jj = 0; jj < HW / 16; jj++) {
        const float2 lj2f = ls2[base2 + jj];
        const unsigned long long lj2 = pack2(lj2f.x, lj2f.y);
        const unsigned long long u2 = fma2(al2, lj2, m2n2);
        float u0, u1;
        unpack2(u2, u0, u1);
        const unsigned long long e2 = pack2(ex2f(u0), ex2f(u1));
        S2 = add2(S2, e2);
        T2 = fma2(lj2, e2, T2);
    }
    float S0, S1, T0, T1;
    unpack2(S2, S0, S1);
    unpack2(T2, T0, T1);
    partS[tid] = S0 + S1;
    partT[tid] = T0 + T1;
    __syncthreads();
    float Ss = 0.0f, Ts = 0.0f;
    #pragma unroll
    for (int k = 0; k < 8; k++) {
        Ss += partS[k * 32 + p];
        Ts += partT[k * 32 + p];
    }
    const float sv = Ts / Ss;

    // out = img + gamma * (vg*sv + bv), register-cached img
    float* ob = out + (size_t)b * C * HW + (size_t)c0 * HW + i;
    #pragma unroll
    for (int cc = 0; cc < 32; cc++) {
        ob[(size_t)cc * HW] = fmaf(gm, fmaf(vgs[c0 + cc], sv, bvs[c0 + cc]), im[cc]);
    }

    // ---- reset counters for next launch (graph replay safe) ----
    if (tid == 0) {
        const unsigned int old = atomicAdd(&g_done, 1u);
        if (old == NATTN - 1) {
            #pragma unroll
            for (int k = 0; k < B; k++) g_cnt1[k] = 0;
            g_flag2 = 0;
            g_done = 0;
        }
    }
}

extern "C" void kernel_launch(void* const* d_in, const int* in_sizes, int n_in,
                              void* d_out, int out_size)
{
    const float* img   = (const float*)d_in[0];
    const float* text  = (const float*)d_in[1];
    const float* l     = (const float*)d_in[2];
    const float* Wg1   = (const float*)d_in[3];
    const float* bg1   = (const float*)d_in[4];
    const float* ln_g  = (const float*)d_in[5];
    const float* ln_b  = (const float*)d_in[6];
    const float* Wg2   = (const float*)d_in[7];
    const float* bg2   = (const float*)d_in[8];
    const float* Wq    = (const float*)d_in[9];
    const float* bq    = (const float*)d_in[10];
    const float* Wk    = (const float*)d_in[11];
    // d_in[12] = bk : cancels in softmax, unused
    const float* Wv    = (const float*)d_in[13];
    const float* bv    = (const float*)d_in[14];
    const float* gamma = (const float*)d_in[15];
    float* out = (float*)d_out;

    fused_kernel<<<NBLK, 256>>>(img, text, l, Wg1, bg1, ln_g, ln_b,
                                Wg2, bg2, Wq, bq, Wk, Wv, bv, gamma, out);
}